// round 15
// baseline (speedup 1.0000x reference)
#include <cuda_runtime.h>
#include <cuda_bf16.h>
#include <stdint.h>

// Problem constants
#define N_TOK   2048
#define DIM     512
#define HOUT    512
#define NEXP    16

// GEMM tiling: CTA 64x64, 4 warps of 32x32, K-chunk 32 (one IMMA k-step)
#define BM      64
#define BN      64
#define KC      32
#define NCHUNK  (DIM / KC)   // 16
#define NSTAGE  3
#define MAX_TILES 48
#define PAD_TOK (MAX_TILES * BM)   // 3072

// smem layout (BYTE offsets)
#define LDSA_B  48                    // A row stride: 32B data + 16 pad (ldsm bank-perfect)
#define A_ARR_B (BM * LDSA_B)         // 3072 (one of q1/q2)
#define A_ST_B  (2 * A_ARR_B)         // 6144 per stage
#define B0_B    (NSTAGE * A_ST_B)     // 18432
#define LDSB_B  48                    // B k-major row stride: 32B data + 16 pad (LDS bank-perfect)
#define B_ARR_B (BN * LDSB_B)         // 3072
#define B_BUF_B (2 * B_ARR_B)         // 6144 per buf (q1+q2)
#define W0_B    (B0_B + 2 * B_BUF_B)  // 30720
#define W_ROW_F 68                    // fp32 W stage row: 64 + 4 pad floats (272B, 16B-aligned)
#define W_ST_B  (KC * W_ROW_F * 4)    // 8704
#define SMEM_BYTES (W0_B + NSTAGE * W_ST_B)   // 56832

// Quantized scratch
__device__ uint4 g_Xq1[N_TOK * DIM / 16];
__device__ uint4 g_Xq2[N_TOK * DIM / 16];
__device__ float g_sx[N_TOK];
__device__ float g_sw[NEXP * HOUT];
__device__ float g_isw[NEXP * HOUT];

__device__ int g_order[PAD_TOK];
__device__ int g_tile_expert[MAX_TILES];

// ---------------------------------------------------------------------------
// PTX helpers (sm_80-era only)
// ---------------------------------------------------------------------------
__device__ __forceinline__ uint32_t smem_u32(const void* p) {
    uint32_t a;
    asm("{ .reg .u64 t; cvta.to.shared.u64 t, %1; cvt.u32.u64 %0, t; }"
        : "=r"(a) : "l"(p));
    return a;
}
__device__ __forceinline__ void ldsm_x4(uint32_t* r, uint32_t addr) {
    asm volatile("ldmatrix.sync.aligned.m8n8.x4.shared.b16 {%0,%1,%2,%3}, [%4];"
                 : "=r"(r[0]), "=r"(r[1]), "=r"(r[2]), "=r"(r[3]) : "r"(addr));
}
__device__ __forceinline__ uint32_t lds32(uint32_t addr) {
    uint32_t v;
    asm volatile("ld.shared.b32 %0, [%1];" : "=r"(v) : "r"(addr));
    return v;
}
__device__ __forceinline__ void mma_s8(int* c, const uint32_t* a,
                                       uint32_t b0, uint32_t b1) {
    asm volatile(
        "mma.sync.aligned.m16n8k32.row.col.s32.s8.s8.s32 "
        "{%0,%1,%2,%3}, {%4,%5,%6,%7}, {%8,%9}, {%0,%1,%2,%3};"
        : "+r"(c[0]), "+r"(c[1]), "+r"(c[2]), "+r"(c[3])
        : "r"(a[0]), "r"(a[1]), "r"(a[2]), "r"(a[3]), "r"(b0), "r"(b1));
}
__device__ __forceinline__ void cp16(uint32_t dst, const void* src,
                                     uint32_t src_bytes) {
    asm volatile("cp.async.cg.shared.global [%0], [%1], 16, %2;"
                 :: "r"(dst), "l"(src), "r"(src_bytes) : "memory");
}
__device__ __forceinline__ void cp_commit() {
    asm volatile("cp.async.commit_group;" ::: "memory");
}
template <int N>
__device__ __forceinline__ void cp_wait() {
    asm volatile("cp.async.wait_group %0;" :: "n"(N) : "memory");
}
__device__ __forceinline__ uint32_t pack4(int a, int b, int c, int d) {
    return (uint32_t)(a & 0xFF) | ((uint32_t)(b & 0xFF) << 8) |
           ((uint32_t)(c & 0xFF) << 16) | ((uint32_t)(d & 0xFF) << 24);
}

// ---------------------------------------------------------------------------
// Bucketing in smem (proven).
// ---------------------------------------------------------------------------
__device__ void bucket_block_fast(const int* __restrict__ idx32)
{
    __shared__ int w[2 * N_TOK];
    __shared__ int ord[PAD_TOK];
    __shared__ int cnt[NEXP], off[NEXP], cur[NEXP];
    __shared__ int odd_or;
    const int t = threadIdx.x;

    if (t == 0) odd_or = 0;
    if (t < NEXP) { cnt[t] = 0; cur[t] = 0; }

    for (int i = t; i < N_TOK; i += 256) w[i] = idx32[i];
    __syncthreads();

    int lor = 0;
    for (int i = t; i < N_TOK / 2; i += 256) lor |= w[2 * i + 1];
    if (lor) atomicOr(&odd_or, 1);
    __syncthreads();

    const int stride = (odd_or == 0) ? 2 : 1;
    if (stride == 2) {
        for (int i = t; i < N_TOK; i += 256) w[N_TOK + i] = idx32[N_TOK + i];
        __syncthreads();
    }

    for (int i = t; i < N_TOK; i += 256)
        atomicAdd(&cnt[w[i * stride] & (NEXP - 1)], 1);
    for (int i = t; i < PAD_TOK; i += 256) ord[i] = -1;
    __syncthreads();

    if (t == 0) {
        int po = 0, tile = 0;
        for (int e = 0; e < NEXP; e++) {
            off[e] = po;
            int ntl = (cnt[e] + BM - 1) / BM;
            for (int k = 0; k < ntl; k++) g_tile_expert[tile++] = e;
            po += ntl * BM;
        }
        for (; tile < MAX_TILES; tile++) g_tile_expert[tile] = -1;
    }
    __syncthreads();

    for (int i = t; i < N_TOK; i += 256) {
        int e = w[i * stride] & (NEXP - 1);
        ord[off[e] + atomicAdd(&cur[e], 1)] = i;
    }
    __syncthreads();

    for (int i = t; i < PAD_TOK; i += 256) g_order[i] = ord[i];
}

// ---------------------------------------------------------------------------
// Pass 1: block 0 = bucket; blocks [1,256] = X two-level int8 quant (warp/row);
// blocks [257,320] = W per-column scale (maxabs over k).
// ---------------------------------------------------------------------------
#define XQ_BLOCKS 256
#define WS_BLOCKS 64
#define PREP_BLOCKS (1 + XQ_BLOCKS + WS_BLOCKS)

__global__ void prep_kernel(const float* __restrict__ X,
                            const float* __restrict__ W,
                            const int* __restrict__ idx32)
{
    const int bid = blockIdx.x;
    const int t = threadIdx.x;

    if (bid == 0) { bucket_block_fast(idx32); return; }

    if (bid <= XQ_BLOCKS) {
        // X quant: warp per row
        const int wid = t >> 5, lane = t & 31;
        const int row = (bid - 1) * 8 + wid;
        float4 v[4];
#pragma unroll
        for (int w4 = 0; w4 < 4; w4++)
            v[w4] = *(const float4*)(X + (size_t)row * DIM + w4 * 128 + lane * 4);
        float mx = 0.f;
#pragma unroll
        for (int w4 = 0; w4 < 4; w4++) {
            mx = fmaxf(mx, fabsf(v[w4].x)); mx = fmaxf(mx, fabsf(v[w4].y));
            mx = fmaxf(mx, fabsf(v[w4].z)); mx = fmaxf(mx, fabsf(v[w4].w));
        }
#pragma unroll
        for (int s = 16; s > 0; s >>= 1)
            mx = fmaxf(mx, __shfl_xor_sync(0xffffffffu, mx, s));
        mx = fmaxf(mx, 1e-20f);
        const float inv = 127.f / mx;
        if (lane == 0) g_sx[row] = mx / 127.f;
        uint32_t* q1o = (uint32_t*)g_Xq1;
        uint32_t* q2o = (uint32_t*)g_Xq2;
#pragma unroll
        for (int w4 = 0; w4 < 4; w4++) {
            float f[4] = {v[w4].x, v[w4].y, v[w4].z, v[w4].w};
            int q1[4], q2[4];
#pragma unroll
            for (int j = 0; j < 4; j++) {
                float sc = f[j] * inv;
                q1[j] = __float2int_rn(sc);
                q2[j] = __float2int_rn((sc - (float)q1[j]) * 128.f);
            }
            q1o[row * 128 + w4 * 32 + lane] = pack4(q1[0], q1[1], q1[2], q1[3]);
            q2o[row * 128 + w4 * 32 + lane] = pack4(q2[0], q2[1], q2[2], q2[3]);
        }
        return;
    }

    // W per-column scale: block b -> expert e, 128-col slice
    __shared__ float cmax[2][128];
    const int b = bid - 1 - XQ_BLOCKS;
    const int e = b >> 2;
    const int c0 = (b & 3) * 128;
    const int col = c0 + (t & 127);
    const int half = t >> 7;
    const float* Wp = W + (size_t)e * DIM * HOUT + col;
    float mx = 0.f;
    for (int k = half * 256; k < half * 256 + 256; k++)
        mx = fmaxf(mx, fabsf(Wp[(size_t)k * HOUT]));
    cmax[half][t & 127] = mx;
    __syncthreads();
    if (t < 128) {
        float m = fmaxf(cmax[0][t], cmax[1][t]);
        m = fmaxf(m, 1e-20f);
        g_sw[e * HOUT + c0 + t] = m / 127.f;
        g_isw[e * HOUT + c0 + t] = 127.f / m;
    }
}

// ---------------------------------------------------------------------------
// Pass 2: IMMA grouped GEMM. A (Xq1/Xq2 int8) 3-stage cp.async; W fp32
// 3-stage cp.async (2-iter prefetch) -> in-smem quantize + TRANSPOSE into
// k-major int8 B tiles (double buffered). One commit group + one barrier
// per iteration (group #c = {A(c+2), W(c+3)}).
// ---------------------------------------------------------------------------
__device__ __forceinline__ void stage_a(uint32_t sdst, int c,
                                        const char* Xq1b, const char* Xq2b,
                                        const int* toks, int tid)
{
    const int k0 = c * KC;
    const int row = tid >> 1;
    const int half = tid & 1;
    const int tok = toks[row];
    const uint32_t nb = (tok >= 0) ? 16u : 0u;
    const size_t src = (size_t)(tok >= 0 ? tok : 0) * DIM + k0 + half * 16;
    const uint32_t d = sdst + (uint32_t)(row * LDSA_B + half * 16);
    cp16(d, Xq1b + src, nb);
    cp16(d + A_ARR_B, Xq2b + src, nb);
}

__device__ __forceinline__ void stage_w(uint32_t sbase, int wst, int c,
                                        const float* Wf, int tid)
{
    const int k0 = c * KC;
    const uint32_t base = sbase + W0_B + (uint32_t)wst * W_ST_B;
#pragma unroll
    for (int t = 0; t < 4; t++) {
        int i = tid + t * 128;          // 0..511: 32 rows x 16 vec4
        int row = i >> 4;
        int c4 = (i & 15) * 4;
        cp16(base + (uint32_t)(row * W_ROW_F + c4) * 4,
             Wf + (size_t)(k0 + row) * HOUT + c4, 16u);
    }
}

// fp32 W stage [32k][68f] -> int8 k-major B tiles [64n][48B] (q1 & q2)
__device__ __forceinline__ void convert_w(uint32_t sbase, int wst, int bufsel,
                                          float invw, int tid)
{
    const uint32_t wb = sbase + W0_B + (uint32_t)wst * W_ST_B;
    const uint32_t bb = sbase + B0_B + (uint32_t)bufsel * B_BUF_B;
    const int n = tid & 63;
#pragma unroll
    for (int it = 0; it < 4; it++) {
        const int w = tid + it * 128;
        const int kq = w >> 6;          // 0..7 (k-group of 4)
        int q1[4], q2[4];
#pragma unroll
        for (int j = 0; j < 4; j++) {
            float f = __uint_as_float(
                lds32(wb + (uint32_t)((kq * 4 + j) * W_ROW_F + n) * 4));
            float sc = f * invw;
            q1[j] = __float2int_rn(sc);
            q2[j] = __float2int_rn((sc - (float)q1[j]) * 128.f);
        }
        const uint32_t d = bb + (uint32_t)(n * LDSB_B + kq * 4);
        asm volatile("st.shared.b32 [%0], %1;"
                     :: "r"(d), "r"(pack4(q1[0], q1[1], q1[2], q1[3])) : "memory");
        asm volatile("st.shared.b32 [%0], %1;"
                     :: "r"(d + B_ARR_B), "r"(pack4(q2[0], q2[1], q2[2], q2[3]))
                     : "memory");
    }
}

__global__ __launch_bounds__(128, 3)
void gemm_imma_kernel(const float* __restrict__ W,
                      const float* __restrict__ Bv,
                      float* __restrict__ Y)
{
    extern __shared__ char smc[];
    __shared__ int toks[BM];

    const int mt = blockIdx.x;
    const int nt = blockIdx.y;
    const int e  = g_tile_expert[mt];
    if (e < 0) return;

    const int tid = threadIdx.x;
    const int wid = tid >> 5;
    const int lid = tid & 31;
    const int ntb = nt * BN;

    if (tid < BM) toks[tid] = g_order[mt * BM + tid];
    __syncthreads();

    const char* Xq1b = (const char*)g_Xq1;
    const char* Xq2b = (const char*)g_Xq2;
    const float* Wf = W + (size_t)e * DIM * HOUT + ntb;
    const float invw = g_isw[e * HOUT + ntb + (tid & 63)];

    const int m_base = (wid >> 1) * 32;
    const int n_base = (wid & 1) * 32;

    const uint32_t sbase = smem_u32(smc);
    const uint32_t aAddr = sbase +
        (uint32_t)((m_base + (lid & 15)) * LDSA_B + ((lid >> 4) << 4));
    const uint32_t bAddr = sbase + B0_B +
        (uint32_t)((n_base + (lid >> 2)) * LDSB_B + (lid & 3) * 4);

    int hh[2][4][4] = {};
    int cr[2][4][4] = {};

    // prologue: group #0 = {A0, W0, W1}; group #1 = {A1, W2}
    stage_a(sbase + 0 * A_ST_B, 0, Xq1b, Xq2b, toks, tid);
    stage_w(sbase, 0, 0, Wf, tid);
    stage_w(sbase, 1, 1, Wf, tid);
    cp_commit();
    stage_a(sbase + 1 * A_ST_B, 1, Xq1b, Xq2b, toks, tid);
    stage_w(sbase, 2, 2, Wf, tid);
    cp_commit();

    int abuf = 0;
    for (int c = 0; c < NCHUNK; c++) {
        cp_wait<1>();
        __syncthreads();
        // groups <= #c complete: A(c), W(c+1) landed; all warps past compute(c-1)

        if (c == 0) {
            convert_w(sbase, 0, 0, invw, tid);
            convert_w(sbase, 1, 1, invw, tid);
            __syncthreads();
        } else if (c + 1 < NCHUNK) {
            convert_w(sbase, (c + 1) % 3, (c + 1) & 1, invw, tid);
        }

        const uint32_t aoff = (uint32_t)(abuf * A_ST_B);
        const uint32_t boff = (uint32_t)((c & 1) * B_BUF_B);

        uint32_t a1[2][4], a2[2][4], b1[4][2], b2[4][2];
#pragma unroll
        for (int mi = 0; mi < 2; mi++) {
            uint32_t ad = aAddr + aoff + (uint32_t)(mi * 16 * LDSA_B);
            ldsm_x4(a1[mi], ad);
            ldsm_x4(a2[mi], ad + A_ARR_B);
        }
#pragma unroll
        for (int np = 0; np < 2; np++) {
            uint32_t bd = bAddr + boff + (uint32_t)(np * 8 * LDSB_B);
            b1[np * 2 + 0][0] = lds32(bd);
            b1[np * 2 + 0][1] = lds32(bd + 16);
            b2[np * 2 + 0][0] = lds32(bd + B_ARR_B);
            b2[np * 2 + 0][1] = lds32(bd + B_ARR_B + 16);
            uint32_t bd2 = bd + (uint32_t)(16 * LDSB_B);
            b1[np * 2 + 1][0] = lds32(bd2);
            b1[np * 2 + 1][1] = lds32(bd2 + 16);
            b2[np * 2 + 1][0] = lds32(bd2 + B_ARR_B);
            b2[np * 2 + 1][1] = lds32(bd2 + B_ARR_B + 16);
        }
        // NOTE: frag ni maps to n-offset ni*8 within warp tile:
        // ni = np*2+h covers n = n_base + (np*8 + h*16)?? -> must match epilogue;
        // we define frag ni at n-offset: ni0->0, ni1->16, ni2->8, ni3->24? No:
        // keep simple mapping ni -> n_off = ni*8 by loading accordingly below.

#pragma unroll
        for (int mi = 0; mi < 2; mi++)
#pragma unroll
            for (int ni = 0; ni < 4; ni++)
                mma_s8(hh[mi][ni], a1[mi], b1[ni][0], b1[ni][1]);
#pragma unroll
        for (int mi = 0; mi < 2; mi++)
#pragma unroll
            for (int ni = 0; ni < 4; ni++)
                mma_s8(cr[mi][ni], a1[mi], b2[ni][0], b2[ni][1]);
#pragma unroll
        for (int mi = 0; mi < 2; mi++)
#pragma unroll
            for (int ni = 0; ni < 4; ni++)
                mma_s8(cr[mi][ni], a2[mi], b1[ni][0], b1[ni][1]);

        if (c + 2 < NCHUNK) {
            int nbuf = abuf + 2; if (nbuf >= NSTAGE) nbuf -= NSTAGE;
            stage_a(sbase + (uint32_t)(nbuf * A_ST_B), c + 2, Xq1b, Xq2b, toks, tid);
        }
        if (c + 3 < NCHUNK)
            stage_w(sbase, (c + 3) % 3, c + 3, Wf, tid);
        cp_commit();

        if (++abuf == NSTAGE) abuf = 0;
    }

    // epilogue: dequant + bias + gathered store
    // frag ni loaded at n-offsets {0,16} for np=0 and {... } -- mapping:
    // ni=0 -> n_off 0, ni=1 -> 16, ni=2 -> 8?  Careful: loads above used
    // np in {0,1} with bd at np*8*LDSB_B and bd2 at +16 rows:
    //   ni=0 -> rows n_base+0..7,  ni=1 -> n_base+16..23,
    //   ni=2 -> n_base+8..15, ni=3 -> n_base+24..31
    const int n_off[4] = {0, 16, 8, 24};
#pragma unroll
    for (int mi = 0; mi < 2; mi++) {
        const int r0 = m_base + mi * 16 + (lid >> 2);
        const int tok0 = toks[r0];
        const int tok1 = toks[r0 + 8];
        const float sx0 = (tok0 >= 0) ? g_sx[tok0] : 0.f;
        const float sx1 = (tok1 >= 0) ? g_sx[tok1] : 0.f;
#pragma unroll
        for (int ni = 0; ni < 4; ni++) {
            const int col = ntb + n_base + n_off[ni] + (lid & 3) * 2;
            const float sw0 = g_sw[e * HOUT + col];
            const float sw1 = g_sw[e * HOUT + col + 1];
            const float2 b2v = *(const float2*)(Bv + (size_t)e * HOUT + col);
            if (tok0 >= 0) {
                float2 o;
                o.x = ((float)hh[mi][ni][0] + (float)cr[mi][ni][0] * 0.0078125f)
                      * (sx0 * sw0) + b2v.x;
                o.y = ((float)hh[mi][ni][1] + (float)cr[mi][ni][1] * 0.0078125f)
                      * (sx0 * sw1) + b2v.y;
                *(float2*)(Y + (size_t)tok0 * HOUT + col) = o;
            }
            if (tok1 >= 0) {
                float2 o;
                o.x = ((float)hh[mi][ni][2] + (float)cr[mi][ni][2] * 0.0078125f)
                      * (sx1 * sw0) + b2v.x;
                o.y = ((float)hh[mi][ni][3] + (float)cr[mi][ni][3] * 0.0078125f)
                      * (sx1 * sw1) + b2v.y;
                *(float2*)(Y + (size_t)tok1 * HOUT + col) = o;
            }
        }
    }
}

extern "C" void kernel_launch(void* const* d_in, const int* in_sizes, int n_in,
                              void* d_out, int out_size)
{
    const float* X   = (const float*)d_in[0];   // inputs (2048, 512) f32
    const int*   idx = (const int*)d_in[1];     // idx (2048) i32/i64 autodetect
    const float* W   = (const float*)d_in[2];   // weights (16, 512, 512) f32
    const float* Bv  = (const float*)d_in[3];   // biases (16, 512) f32
    float*       Y   = (float*)d_out;           // out (2048, 512) f32

    cudaFuncSetAttribute(gemm_imma_kernel,
                         cudaFuncAttributeMaxDynamicSharedMemorySize, SMEM_BYTES);

    prep_kernel<<<PREP_BLOCKS, 256>>>(X, W, idx);

    dim3 grid(MAX_TILES, HOUT / BN);
    gemm_imma_kernel<<<grid, 128, SMEM_BYTES>>>(W, Bv, Y);
}

// round 17
// speedup vs baseline: 1.1884x; 1.1884x over previous
#include <cuda_runtime.h>
#include <cuda_bf16.h>
#include <stdint.h>

// Problem constants
#define N_TOK   2048
#define DIM     512
#define HOUT    512
#define NEXP    16

// Tiling: CTA 64x64 (4 warps, each 32x32), K chunk 32, warp-private pipeline
#define BM      64
#define BN      64
#define KC      32
#define NCHUNK  (DIM / KC)   // 16
#define MAX_TILES 48
#define PAD_TOK (MAX_TILES * BM)   // 3072

// Per-warp smem slice (bytes)
#define WARP_SM 28672
#define A_OFF   0        // + stage*5120 ; hi +0 (32 rows x 80B), lo +2560
#define W_OFF   10240    // + stage*4096 ; 32 k-rows x 128B fp32
#define B_OFF   18432    // + buf*5120   ; hi +0 (32 n-rows x 80B), lo +2560
#define SMEM_BYTES (4 * WARP_SM)   // 114688 -> 2 CTAs/SM

// X split scratch
#define XELEMS (N_TOK * DIM)
__device__ uint4 g_Xhi4[XELEMS / 8];
__device__ uint4 g_Xlo4[XELEMS / 8];

__device__ int g_order[PAD_TOK];
__device__ int g_tile_expert[MAX_TILES];

// ---------------------------------------------------------------------------
// PTX helpers (sm_80-era only)
// ---------------------------------------------------------------------------
__device__ __forceinline__ uint32_t smem_u32(const void* p) {
    uint32_t a;
    asm("{ .reg .u64 t; cvta.to.shared.u64 t, %1; cvt.u32.u64 %0, t; }"
        : "=r"(a) : "l"(p));
    return a;
}
__device__ __forceinline__ void ldsm_x4(uint32_t* r, uint32_t addr) {
    asm volatile("ldmatrix.sync.aligned.m8n8.x4.shared.b16 {%0,%1,%2,%3}, [%4];"
                 : "=r"(r[0]), "=r"(r[1]), "=r"(r[2]), "=r"(r[3]) : "r"(addr));
}
__device__ __forceinline__ uint32_t lds32(uint32_t addr) {
    uint32_t v;
    asm volatile("ld.shared.b32 %0, [%1];" : "=r"(v) : "r"(addr));
    return v;
}
__device__ __forceinline__ void mma_bf16(float* c, const uint32_t* a,
                                         uint32_t b0, uint32_t b1) {
    asm volatile(
        "mma.sync.aligned.m16n8k16.row.col.f32.bf16.bf16.f32 "
        "{%0,%1,%2,%3}, {%4,%5,%6,%7}, {%8,%9}, {%0,%1,%2,%3};"
        : "+f"(c[0]), "+f"(c[1]), "+f"(c[2]), "+f"(c[3])
        : "r"(a[0]), "r"(a[1]), "r"(a[2]), "r"(a[3]), "r"(b0), "r"(b1));
}
__device__ __forceinline__ void cp16(uint32_t dst, const void* src,
                                     uint32_t src_bytes) {
    asm volatile("cp.async.cg.shared.global [%0], [%1], 16, %2;"
                 :: "r"(dst), "l"(src), "r"(src_bytes) : "memory");
}
__device__ __forceinline__ void cp_commit() {
    asm volatile("cp.async.commit_group;" ::: "memory");
}
template <int N>
__device__ __forceinline__ void cp_wait() {
    asm volatile("cp.async.wait_group %0;" :: "n"(N) : "memory");
}

// ---------------------------------------------------------------------------
// Bucketing in smem (proven).
// ---------------------------------------------------------------------------
__device__ void bucket_block_fast(const int* __restrict__ idx32)
{
    __shared__ int w[2 * N_TOK];
    __shared__ int ord[PAD_TOK];
    __shared__ int cnt[NEXP], off[NEXP], cur[NEXP];
    __shared__ int odd_or;
    const int t = threadIdx.x;

    if (t == 0) odd_or = 0;
    if (t < NEXP) { cnt[t] = 0; cur[t] = 0; }

    for (int i = t; i < N_TOK; i += 256) w[i] = idx32[i];
    __syncthreads();

    int lor = 0;
    for (int i = t; i < N_TOK / 2; i += 256) lor |= w[2 * i + 1];
    if (lor) atomicOr(&odd_or, 1);
    __syncthreads();

    const int stride = (odd_or == 0) ? 2 : 1;
    if (stride == 2) {
        for (int i = t; i < N_TOK; i += 256) w[N_TOK + i] = idx32[N_TOK + i];
        __syncthreads();
    }

    for (int i = t; i < N_TOK; i += 256)
        atomicAdd(&cnt[w[i * stride] & (NEXP - 1)], 1);
    for (int i = t; i < PAD_TOK; i += 256) ord[i] = -1;
    __syncthreads();

    if (t == 0) {
        int po = 0, tile = 0;
        for (int e = 0; e < NEXP; e++) {
            off[e] = po;
            int ntl = (cnt[e] + BM - 1) / BM;
            for (int k = 0; k < ntl; k++) g_tile_expert[tile++] = e;
            po += ntl * BM;
        }
        for (; tile < MAX_TILES; tile++) g_tile_expert[tile] = -1;
    }
    __syncthreads();

    for (int i = t; i < N_TOK; i += 256) {
        int e = w[i * stride] & (NEXP - 1);
        ord[off[e] + atomicAdd(&cur[e], 1)] = i;
    }
    __syncthreads();

    for (int i = t; i < PAD_TOK; i += 256) g_order[i] = ord[i];
}

// ---------------------------------------------------------------------------
// Pass 1: block 0 buckets; blocks [1, XCONV] split X into bf16 hi/lo.
// ---------------------------------------------------------------------------
#define XCONV (XELEMS / 8 / 256)   // 512

__global__ void prep_kernel(const float4* __restrict__ X,
                            const int* __restrict__ idx32)
{
    if (blockIdx.x == 0) {
        bucket_block_fast(idx32);
        return;
    }
    const int j = (blockIdx.x - 1) * 256 + threadIdx.x;
    float4 v0 = X[2 * j];
    float4 v1 = X[2 * j + 1];
    float f[8] = {v0.x, v0.y, v0.z, v0.w, v1.x, v1.y, v1.z, v1.w};
    __nv_bfloat16 h[8], l[8];
#pragma unroll
    for (int q = 0; q < 8; q++) {
        h[q] = __float2bfloat16(f[q]);
        l[q] = __float2bfloat16(f[q] - __bfloat162float(h[q]));
    }
    uint4 uh, ul;
    uh.x = ((uint32_t)*(uint16_t*)&h[1] << 16) | *(uint16_t*)&h[0];
    uh.y = ((uint32_t)*(uint16_t*)&h[3] << 16) | *(uint16_t*)&h[2];
    uh.z = ((uint32_t)*(uint16_t*)&h[5] << 16) | *(uint16_t*)&h[4];
    uh.w = ((uint32_t)*(uint16_t*)&h[7] << 16) | *(uint16_t*)&h[6];
    ul.x = ((uint32_t)*(uint16_t*)&l[1] << 16) | *(uint16_t*)&l[0];
    ul.y = ((uint32_t)*(uint16_t*)&l[3] << 16) | *(uint16_t*)&l[2];
    ul.z = ((uint32_t)*(uint16_t*)&l[5] << 16) | *(uint16_t*)&l[4];
    ul.w = ((uint32_t)*(uint16_t*)&l[7] << 16) | *(uint16_t*)&l[6];
    g_Xhi4[j] = uh;
    g_Xlo4[j] = ul;
}

// ---------------------------------------------------------------------------
// Pass 2: warp-autonomous HMMA GEMM. No __syncthreads in the mainloop: each
// warp owns a private smem slice and pipelines with its own cp.async groups.
// Per iter c: compute(c) -> issue {A(c+2),W(c+2)} -> wait -> convert W(c+1).
// ---------------------------------------------------------------------------
__device__ __forceinline__ void stage_aw(uint32_t wbase, int c, int st,
                                         const char* Xhi, const char* Xlo,
                                         const char* WfB,
                                         const int* toks, int m_base, int lane)
{
    const uint32_t ab = wbase + (uint32_t)(st * 5120);
#pragma unroll
    for (int i = 0; i < 4; i++) {
        int idx = lane + i * 32;        // 0..127: 32 rows x 4 x 16B
        int row = idx >> 2, q = idx & 3;
        int tok = toks[m_base + row];
        uint32_t nb = (tok >= 0) ? 16u : 0u;
        size_t src = (size_t)(tok >= 0 ? tok : 0) * (DIM * 2) + c * 64 + q * 16;
        uint32_t d = ab + (uint32_t)(row * 80 + q * 16);
        cp16(d, Xhi + src, nb);
        cp16(d + 2560, Xlo + src, nb);
    }
    const uint32_t wb = wbase + W_OFF + (uint32_t)(st * 4096);
#pragma unroll
    for (int i = 0; i < 8; i++) {
        int idx = lane + i * 32;        // 0..255: 32 k-rows x 8 x 16B
        int kr = idx >> 3, q = idx & 7;
        cp16(wb + (uint32_t)(kr * 128 + q * 16),
             WfB + (size_t)(c * KC + kr) * (HOUT * 4) + q * 16, 16u);
    }
}

// W fp32 stage [32k][32n] -> B bf16 hi/lo k-major [32n][80B]
__device__ __forceinline__ void convert_w(uint32_t wbase, int st, int buf,
                                          int lane)
{
    const uint32_t wb = wbase + W_OFF + (uint32_t)(st * 4096) + lane * 4;
    const uint32_t bb = wbase + B_OFF + (uint32_t)(buf * 5120) + lane * 80;
#pragma unroll
    for (int j = 0; j < 8; j++) {
        float f[4];
#pragma unroll
        for (int q = 0; q < 4; q++)
            f[q] = __uint_as_float(lds32(wb + (uint32_t)((j * 4 + q) * 128)));
        __nv_bfloat16 h[4], l[4];
#pragma unroll
        for (int q = 0; q < 4; q++) {
            h[q] = __float2bfloat16(f[q]);
            l[q] = __float2bfloat16(f[q] - __bfloat162float(h[q]));
        }
        uint32_t uh0 = ((uint32_t)*(uint16_t*)&h[1] << 16) | *(uint16_t*)&h[0];
        uint32_t uh1 = ((uint32_t)*(uint16_t*)&h[3] << 16) | *(uint16_t*)&h[2];
        uint32_t ul0 = ((uint32_t)*(uint16_t*)&l[1] << 16) | *(uint16_t*)&l[0];
        uint32_t ul1 = ((uint32_t)*(uint16_t*)&l[3] << 16) | *(uint16_t*)&l[2];
        asm volatile("st.shared.v2.b32 [%0], {%1, %2};"
                     :: "r"(bb + (uint32_t)(j * 8)), "r"(uh0), "r"(uh1)
                     : "memory");
        asm volatile("st.shared.v2.b32 [%0], {%1, %2};"
                     :: "r"(bb + 2560u + (uint32_t)(j * 8)), "r"(ul0), "r"(ul1)
                     : "memory");
    }
}

__global__ __launch_bounds__(128, 2)
void gemm_hmma_kernel(const float* __restrict__ W,
                      const float* __restrict__ Bv,
                      float* __restrict__ Y)
{
    extern __shared__ char smc[];
    __shared__ int toks[BM];

    const int mt = blockIdx.x;
    const int nt = blockIdx.y;
    const int e  = g_tile_expert[mt];
    if (e < 0) return;

    const int tid = threadIdx.x;
    const int wid = tid >> 5;          // 0..3
    const int lid = tid & 31;
    const int ntb = nt * BN;

    if (tid < BM) toks[tid] = g_order[mt * BM + tid];
    __syncthreads();                   // only CTA barrier (toks publish)

    const char* Xhi = (const char*)g_Xhi4;
    const char* Xlo = (const char*)g_Xlo4;

    const int m_base = (wid >> 1) * 32;
    const int wn     = (wid & 1) * 32;
    const char* WfB = (const char*)(W + (size_t)e * DIM * HOUT + ntb + wn);

    const uint32_t wbase = smem_u32(smc) + (uint32_t)(wid * WARP_SM);
    // ldsm lane addresses
    const uint32_t aLane = (uint32_t)((lid & 15) * 80 + ((lid >> 4) << 4));
    const uint32_t bLane = (uint32_t)((((lid >> 4) << 3) + (lid & 7)) * 80 +
                                      (((lid >> 3) & 1) << 4));

    float acc[2][4][4] = {};

    // prologue: group0 = {A0,W0}, group1 = {A1,W1}
    stage_aw(wbase, 0, 0, Xhi, Xlo, WfB, toks, m_base, lid);
    cp_commit();
    stage_aw(wbase, 1, 1, Xhi, Xlo, WfB, toks, m_base, lid);
    cp_commit();
    cp_wait<1>();                      // group0 done
    __syncwarp();
    convert_w(wbase, 0, 0, lid);       // W0 -> B buf0
    __syncwarp();

    for (int c = 0; c < NCHUNK; c++) {
        const uint32_t abase = wbase + (uint32_t)((c & 1) * 5120);
        const uint32_t bbase = wbase + B_OFF + (uint32_t)((c & 1) * 5120);

        // ---- compute chunk c ----
#pragma unroll
        for (int ks = 0; ks < 2; ks++) {
            uint32_t ah[2][4], al[2][4], bh[2][4], bl[2][4];
#pragma unroll
            for (int mi = 0; mi < 2; mi++) {
                uint32_t ad = abase + aLane + (uint32_t)(mi * 16 * 80 + ks * 32);
                ldsm_x4(ah[mi], ad);
                ldsm_x4(al[mi], ad + 2560);
            }
#pragma unroll
            for (int nh = 0; nh < 2; nh++) {
                uint32_t bd = bbase + bLane + (uint32_t)(nh * 16 * 80 + ks * 32);
                ldsm_x4(bh[nh], bd);
                ldsm_x4(bl[nh], bd + 2560);
            }
#pragma unroll
            for (int mi = 0; mi < 2; mi++)
#pragma unroll
                for (int nh = 0; nh < 2; nh++) {
                    mma_bf16(acc[mi][nh * 2 + 0], ah[mi], bh[nh][0], bh[nh][1]);
                    mma_bf16(acc[mi][nh * 2 + 1], ah[mi], bh[nh][2], bh[nh][3]);
                }
#pragma unroll
            for (int mi = 0; mi < 2; mi++)
#pragma unroll
                for (int nh = 0; nh < 2; nh++) {
                    mma_bf16(acc[mi][nh * 2 + 0], ah[mi], bl[nh][0], bl[nh][1]);
                    mma_bf16(acc[mi][nh * 2 + 1], ah[mi], bl[nh][2], bl[nh][3]);
                }
#pragma unroll
            for (int mi = 0; mi < 2; mi++)
#pragma unroll
                for (int nh = 0; nh < 2; nh++) {
                    mma_bf16(acc[mi][nh * 2 + 0], al[mi], bh[nh][0], bh[nh][1]);
                    mma_bf16(acc[mi][nh * 2 + 1], al[mi], bh[nh][2], bh[nh][3]);
                }
        }

        // ---- issue loads for c+2 into the A/W stage just consumed ----
        if (c + 2 < NCHUNK)
            stage_aw(wbase, c + 2, c & 1, Xhi, Xlo, WfB, toks, m_base, lid);
        cp_commit();                   // group (c+2), possibly empty

        // ---- wait for {A(c+1), W(c+1)}, then convert W(c+1) ----
        cp_wait<1>();
        __syncwarp();
        if (c + 1 < NCHUNK)
            convert_w(wbase, (c + 1) & 1, (c + 1) & 1, lid);
        __syncwarp();
    }

    // epilogue: bias + gathered store
#pragma unroll
    for (int mi = 0; mi < 2; mi++) {
        const int r0 = m_base + mi * 16 + (lid >> 2);
        const int tok0 = toks[r0];
        const int tok1 = toks[r0 + 8];
#pragma unroll
        for (int nh = 0; nh < 2; nh++)
#pragma unroll
            for (int t = 0; t < 2; t++) {
                const int ni = nh * 2 + t;
                const int col = ntb + wn + nh * 16 + t * 8 + (lid & 3) * 2;
                const float2 b2 = *(const float2*)(Bv + (size_t)e * HOUT + col);
                if (tok0 >= 0) {
                    float2 o = {acc[mi][ni][0] + b2.x, acc[mi][ni][1] + b2.y};
                    *(float2*)(Y + (size_t)tok0 * HOUT + col) = o;
                }
                if (tok1 >= 0) {
                    float2 o = {acc[mi][ni][2] + b2.x, acc[mi][ni][3] + b2.y};
                    *(float2*)(Y + (size_t)tok1 * HOUT + col) = o;
                }
            }
    }
}

extern "C" void kernel_launch(void* const* d_in, const int* in_sizes, int n_in,
                              void* d_out, int out_size)
{
    const float* X   = (const float*)d_in[0];   // inputs (2048, 512) f32
    const int*   idx = (const int*)d_in[1];     // idx (2048) i32/i64 autodetect
    const float* W   = (const float*)d_in[2];   // weights (16, 512, 512) f32
    const float* Bv  = (const float*)d_in[3];   // biases (16, 512) f32
    float*       Y   = (float*)d_out;           // out (2048, 512) f32

    cudaFuncSetAttribute(gemm_hmma_kernel,
                         cudaFuncAttributeMaxDynamicSharedMemorySize, SMEM_BYTES);

    prep_kernel<<<XCONV + 1, 256>>>((const float4*)X, idx);

    dim3 grid(MAX_TILES, HOUT / BN);
    gemm_hmma_kernel<<<grid, 128, SMEM_BYTES>>>(W, Bv, Y);
}